// round 1
// baseline (speedup 1.0000x reference)
#include <cuda_runtime.h>
#include <math.h>

// Problem constants
#define TT 1024            // tokens (B*S)
#define HH 2048            // hidden
#define II 7168            // intermediate
#define EE 8               // experts
#define RR 159             // low rank
#define ERR (EE * RR)      // 1272

// ---------------------------------------------------------------------------
// Scratch (device globals; no runtime allocation allowed)
// ---------------------------------------------------------------------------
__device__ float g_base_gate[(size_t)TT * II];      // 29.4 MB
__device__ float g_base_up  [(size_t)TT * II];      // 29.4 MB
__device__ float g_hmid     [(size_t)TT * 2 * II];  // 58.7 MB, indexed by slot=t*2+k
__device__ float g_t1       [(size_t)TT * ERR];     // dense over all experts
__device__ float g_t3       [(size_t)TT * ERR];
__device__ float g_t2       [(size_t)TT * 2 * RR];  // per-slot
__device__ float g_w        [TT * 2];               // comb weight per slot
__device__ int   g_elist    [EE][TT];               // packed token*2+slot
__device__ int   g_ecount   [EE];
__device__ float g_logits_s [TT * EE];              // fallback if out has no logits region

// ---------------------------------------------------------------------------
// Init: zero expert counters (must happen each replay)
// ---------------------------------------------------------------------------
__global__ void init_counts() {
    if (threadIdx.x < EE) g_ecount[threadIdx.x] = 0;
}

// ---------------------------------------------------------------------------
// Router: one warp per token. logits, top-2, normalized weights, expert lists.
// ---------------------------------------------------------------------------
__global__ void router_kernel(const float* __restrict__ x,
                              const float* __restrict__ gw,
                              float* __restrict__ logits_out) {
    int warp = threadIdx.x >> 5;
    int lane = threadIdx.x & 31;
    int t = blockIdx.x * (blockDim.x >> 5) + warp;
    if (t >= TT) return;
    const float* xr = x + (size_t)t * HH;
    float lg[EE];
#pragma unroll
    for (int e = 0; e < EE; e++) {
        const float* w = gw + e * HH;
        float s = 0.f;
        for (int h = lane; h < HH; h += 32) s += xr[h] * w[h];
#pragma unroll
        for (int o = 16; o > 0; o >>= 1) s += __shfl_xor_sync(0xffffffffu, s, o);
        lg[e] = s;
    }
    if (lane == 0) {
#pragma unroll
        for (int e = 0; e < EE; e++) logits_out[t * EE + e] = lg[e];
        // top-2 of logits == top-2 of softmax (monotone); ties -> lower index
        int i0 = 0;
#pragma unroll
        for (int e = 1; e < EE; e++) if (lg[e] > lg[i0]) i0 = e;
        int i1 = (i0 == 0) ? 1 : 0;
#pragma unroll
        for (int e = 0; e < EE; e++) if (e != i0 && lg[e] > lg[i1]) i1 = e;
        // w0 = p0/(p0+p1): softmax denominator cancels
        float r = expf(lg[i1] - lg[i0]);     // <= 1
        float w0 = 1.f / (1.f + r);
        float w1 = r / (1.f + r);
        g_w[t * 2 + 0] = w0;
        g_w[t * 2 + 1] = w1;
        int p0 = atomicAdd(&g_ecount[i0], 1);
        g_elist[i0][p0] = t * 2 + 0;
        int p1 = atomicAdd(&g_ecount[i1], 1);
        g_elist[i1][p1] = t * 2 + 1;
    }
}

// ---------------------------------------------------------------------------
// SGEMM NT: C[M,N] = A[M,K] * B[N,K]^T, fp32, 128x128x16 tiles, 256 threads,
// 8x8 per thread, register prefetch double-buffer.
// SUM2: A row m is (Arow[m*2K] + Arow[m*2K + K])  (used to sum the two hmid slots)
// Requires K % 16 == 0.
// ---------------------------------------------------------------------------
template <bool SUM2>
__global__ void __launch_bounds__(256) sgemm_nt(const float* __restrict__ A,
                                                const float* __restrict__ B,
                                                float* __restrict__ C,
                                                int M, int N, int K) {
    __shared__ float As[16][132];
    __shared__ float Bs[16][132];
    const int bm = blockIdx.y * 128;
    const int bn = blockIdx.x * 128;
    const int tid = threadIdx.x;
    const int tx = tid & 15;
    const int ty = tid >> 4;
    const int lr = tid >> 2;           // 0..63
    const int lc = (tid & 3) << 2;     // 0,4,8,12

    float acc[8][8];
#pragma unroll
    for (int i = 0; i < 8; i++)
#pragma unroll
        for (int j = 0; j < 8; j++) acc[i][j] = 0.f;

    float4 pa[2], pb[2];
#pragma unroll
    for (int i = 0; i < 2; i++) {
        int row = lr + i * 64;
        int gm = bm + row;
        if (gm < M) {
            const float* ap = A + (size_t)gm * (SUM2 ? 2 * K : K) + lc;
            pa[i] = *(const float4*)ap;
            if (SUM2) {
                float4 v2 = *(const float4*)(ap + K);
                pa[i].x += v2.x; pa[i].y += v2.y; pa[i].z += v2.z; pa[i].w += v2.w;
            }
        } else pa[i] = make_float4(0.f, 0.f, 0.f, 0.f);
        int gn = bn + row;
        pb[i] = (gn < N) ? *(const float4*)(B + (size_t)gn * K + lc)
                         : make_float4(0.f, 0.f, 0.f, 0.f);
    }

    for (int k0 = 0; k0 < K; k0 += 16) {
#pragma unroll
        for (int i = 0; i < 2; i++) {
            int row = lr + i * 64;
            As[lc + 0][row] = pa[i].x; As[lc + 1][row] = pa[i].y;
            As[lc + 2][row] = pa[i].z; As[lc + 3][row] = pa[i].w;
            Bs[lc + 0][row] = pb[i].x; Bs[lc + 1][row] = pb[i].y;
            Bs[lc + 2][row] = pb[i].z; Bs[lc + 3][row] = pb[i].w;
        }
        __syncthreads();

        int k1 = k0 + 16;
        if (k1 < K) {
#pragma unroll
            for (int i = 0; i < 2; i++) {
                int row = lr + i * 64;
                int gm = bm + row;
                if (gm < M) {
                    const float* ap = A + (size_t)gm * (SUM2 ? 2 * K : K) + k1 + lc;
                    pa[i] = *(const float4*)ap;
                    if (SUM2) {
                        float4 v2 = *(const float4*)(ap + K);
                        pa[i].x += v2.x; pa[i].y += v2.y; pa[i].z += v2.z; pa[i].w += v2.w;
                    }
                } else pa[i] = make_float4(0.f, 0.f, 0.f, 0.f);
                int gn = bn + row;
                pb[i] = (gn < N) ? *(const float4*)(B + (size_t)gn * K + k1 + lc)
                                 : make_float4(0.f, 0.f, 0.f, 0.f);
            }
        }

#pragma unroll
        for (int kk = 0; kk < 16; kk++) {
            float4 a0 = *(const float4*)&As[kk][ty * 4];
            float4 a1 = *(const float4*)&As[kk][64 + ty * 4];
            float4 b0 = *(const float4*)&Bs[kk][tx * 4];
            float4 b1 = *(const float4*)&Bs[kk][64 + tx * 4];
            float av[8] = {a0.x, a0.y, a0.z, a0.w, a1.x, a1.y, a1.z, a1.w};
            float bv[8] = {b0.x, b0.y, b0.z, b0.w, b1.x, b1.y, b1.z, b1.w};
#pragma unroll
            for (int i = 0; i < 8; i++)
#pragma unroll
                for (int j = 0; j < 8; j++) acc[i][j] += av[i] * bv[j];
        }
        __syncthreads();
    }

#pragma unroll
    for (int i = 0; i < 8; i++) {
        int row = (i < 4) ? (ty * 4 + i) : (64 + ty * 4 + i - 4);
        int gm = bm + row;
        if (gm >= M) continue;
#pragma unroll
        for (int j = 0; j < 8; j++) {
            int col = (j < 4) ? (tx * 4 + j) : (64 + tx * 4 + j - 4);
            int gn = bn + col;
            if (gn < N) C[(size_t)gm * N + gn] = acc[i][j];
        }
    }
}

// ---------------------------------------------------------------------------
// Per-expert gathered GEMM (dual): for expert e, slot tile (BM=64) x i-tile (BN=64)
//   dG = t1_e @ du1[e]^T,  dU = t3_e @ du3[e]^T   (K = R = 159)
// Epilogue: hmid[slot, i] = w * silu(base_gate + dG) * (base_up + dU)
// ---------------------------------------------------------------------------
__global__ void __launch_bounds__(256) expert_gateup_kernel(const float* __restrict__ du1,
                                                            const float* __restrict__ du3) {
    const int e = blockIdx.z;
    const int ne = g_ecount[e];
    const int m0 = blockIdx.y * 64;
    if (m0 >= ne) return;
    const int n0 = blockIdx.x * 64;

    __shared__ int   s_tk[64];
    __shared__ float s_w[64];
    __shared__ float A1s[16][68], A3s[16][68], B1s[16][68], B3s[16][68];

    const int tid = threadIdx.x;
    if (tid < 64) {
        int gm = m0 + tid;
        if (gm < ne) {
            int tk = g_elist[e][gm];
            s_tk[tid] = tk;
            s_w[tid] = g_w[tk];
        } else {
            s_tk[tid] = -1;
            s_w[tid] = 0.f;
        }
    }
    __syncthreads();

    const int tx = tid & 15;
    const int ty = tid >> 4;
    const float* du1e = du1 + (size_t)e * II * RR;
    const float* du3e = du3 + (size_t)e * II * RR;

    float acc1[4][4] = {}, acc3[4][4] = {};

    for (int k0 = 0; k0 < RR; k0 += 16) {
#pragma unroll
        for (int i = 0; i < 4; i++) {
            int elem = tid + i * 256;
            int r = elem >> 4;
            int kk = elem & 15;
            int k = k0 + kk;
            int tk = s_tk[r];
            float v1 = 0.f, v3 = 0.f;
            if (tk >= 0 && k < RR) {
                size_t off = (size_t)(tk >> 1) * ERR + (size_t)e * RR + k;
                v1 = g_t1[off];
                v3 = g_t3[off];
            }
            A1s[kk][r] = v1; A3s[kk][r] = v3;
            float b1 = 0.f, b3 = 0.f;
            if (k < RR) {
                size_t boff = (size_t)(n0 + r) * RR + k;
                b1 = du1e[boff]; b3 = du3e[boff];
            }
            B1s[kk][r] = b1; B3s[kk][r] = b3;
        }
        __syncthreads();
#pragma unroll
        for (int kk = 0; kk < 16; kk++) {
            float4 a1 = *(const float4*)&A1s[kk][ty * 4];
            float4 a3 = *(const float4*)&A3s[kk][ty * 4];
            float4 b1 = *(const float4*)&B1s[kk][tx * 4];
            float4 b3 = *(const float4*)&B3s[kk][tx * 4];
            float a1v[4] = {a1.x, a1.y, a1.z, a1.w};
            float a3v[4] = {a3.x, a3.y, a3.z, a3.w};
            float b1v[4] = {b1.x, b1.y, b1.z, b1.w};
            float b3v[4] = {b3.x, b3.y, b3.z, b3.w};
#pragma unroll
            for (int i = 0; i < 4; i++)
#pragma unroll
                for (int j = 0; j < 4; j++) {
                    acc1[i][j] += a1v[i] * b1v[j];
                    acc3[i][j] += a3v[i] * b3v[j];
                }
        }
        __syncthreads();
    }

#pragma unroll
    for (int i = 0; i < 4; i++) {
        int r = ty * 4 + i;
        int tk = s_tk[r];
        if (tk < 0) continue;
        int t = tk >> 1;
        float w = s_w[r];
#pragma unroll
        for (int j = 0; j < 4; j++) {
            int gi = n0 + tx * 4 + j;
            size_t off = (size_t)t * II + gi;
            float g = g_base_gate[off] + acc1[i][j];
            float u = g_base_up[off]  + acc3[i][j];
            float s = g / (1.f + expf(-g));   // silu
            g_hmid[(size_t)tk * II + gi] = w * s * u;
        }
    }
}

// ---------------------------------------------------------------------------
// Per-expert gathered GEMM: t2[slot, r] = hmid[slot, :] . dv2[e, r, :]  (K = I)
// ---------------------------------------------------------------------------
__global__ void __launch_bounds__(256) expert_t2_kernel(const float* __restrict__ dv2) {
    const int e = blockIdx.z;
    const int ne = g_ecount[e];
    const int m0 = blockIdx.y * 64;
    if (m0 >= ne) return;
    const int n0 = blockIdx.x * 64;

    __shared__ int   s_tk[64];
    __shared__ float As[16][68], Bs[16][68];

    const int tid = threadIdx.x;
    if (tid < 64) {
        int gm = m0 + tid;
        s_tk[tid] = (gm < ne) ? g_elist[e][gm] : -1;
    }
    __syncthreads();

    const int tx = tid & 15;
    const int ty = tid >> 4;
    const float* dv2e = dv2 + (size_t)e * RR * II;

    float acc[4][4] = {};

    for (int k0 = 0; k0 < II; k0 += 16) {
#pragma unroll
        for (int i = 0; i < 4; i++) {
            int elem = tid + i * 256;
            int r = elem >> 4;
            int kk = elem & 15;
            int k = k0 + kk;
            int tk = s_tk[r];
            As[kk][r] = (tk >= 0) ? g_hmid[(size_t)tk * II + k] : 0.f;
            int gr = n0 + r;
            Bs[kk][r] = (gr < RR) ? dv2e[(size_t)gr * II + k] : 0.f;
        }
        __syncthreads();
#pragma unroll
        for (int kk = 0; kk < 16; kk++) {
            float4 a = *(const float4*)&As[kk][ty * 4];
            float4 b = *(const float4*)&Bs[kk][tx * 4];
            float av[4] = {a.x, a.y, a.z, a.w};
            float bv[4] = {b.x, b.y, b.z, b.w};
#pragma unroll
            for (int i = 0; i < 4; i++)
#pragma unroll
                for (int j = 0; j < 4; j++) acc[i][j] += av[i] * bv[j];
        }
        __syncthreads();
    }

#pragma unroll
    for (int i = 0; i < 4; i++) {
        int tk = s_tk[ty * 4 + i];
        if (tk < 0) continue;
#pragma unroll
        for (int j = 0; j < 4; j++) {
            int gr = n0 + tx * 4 + j;
            if (gr < RR) g_t2[(size_t)tk * RR + gr] = acc[i][j];
        }
    }
}

// ---------------------------------------------------------------------------
// Per-expert gathered GEMM: out[t, h] += t2[slot, :] . du2[e, h, :]  (K = R)
// atomicAdd onto the shared-downproj result (exactly 2 adds per element).
// ---------------------------------------------------------------------------
__global__ void __launch_bounds__(256) expert_down_kernel(const float* __restrict__ du2,
                                                          float* __restrict__ out) {
    const int e = blockIdx.z;
    const int ne = g_ecount[e];
    const int m0 = blockIdx.y * 64;
    if (m0 >= ne) return;
    const int n0 = blockIdx.x * 64;

    __shared__ int   s_tk[64];
    __shared__ float As[16][68], Bs[16][68];

    const int tid = threadIdx.x;
    if (tid < 64) {
        int gm = m0 + tid;
        s_tk[tid] = (gm < ne) ? g_elist[e][gm] : -1;
    }
    __syncthreads();

    const int tx = tid & 15;
    const int ty = tid >> 4;
    const float* du2e = du2 + (size_t)e * HH * RR;

    float acc[4][4] = {};

    for (int k0 = 0; k0 < RR; k0 += 16) {
#pragma unroll
        for (int i = 0; i < 4; i++) {
            int elem = tid + i * 256;
            int r = elem >> 4;
            int kk = elem & 15;
            int k = k0 + kk;
            int tk = s_tk[r];
            As[kk][r] = (tk >= 0 && k < RR) ? g_t2[(size_t)tk * RR + k] : 0.f;
            Bs[kk][r] = (k < RR) ? du2e[(size_t)(n0 + r) * RR + k] : 0.f;
        }
        __syncthreads();
#pragma unroll
        for (int kk = 0; kk < 16; kk++) {
            float4 a = *(const float4*)&As[kk][ty * 4];
            float4 b = *(const float4*)&Bs[kk][tx * 4];
            float av[4] = {a.x, a.y, a.z, a.w};
            float bv[4] = {b.x, b.y, b.z, b.w};
#pragma unroll
            for (int i = 0; i < 4; i++)
#pragma unroll
                for (int j = 0; j < 4; j++) acc[i][j] += av[i] * bv[j];
        }
        __syncthreads();
    }

#pragma unroll
    for (int i = 0; i < 4; i++) {
        int tk = s_tk[ty * 4 + i];
        if (tk < 0) continue;
        int t = tk >> 1;
#pragma unroll
        for (int j = 0; j < 4; j++) {
            int gh = n0 + tx * 4 + j;
            atomicAdd(&out[(size_t)t * HH + gh], acc[i][j]);
        }
    }
}

// ---------------------------------------------------------------------------
// Launch
// ---------------------------------------------------------------------------
extern "C" void kernel_launch(void* const* d_in, const int* in_sizes, int n_in,
                              void* d_out, int out_size) {
    (void)in_sizes; (void)n_in;
    const float* x   = (const float*)d_in[0];
    const float* gw  = (const float*)d_in[1];
    const float* Wm1 = (const float*)d_in[2];
    const float* Wm2 = (const float*)d_in[3];
    const float* Wm3 = (const float*)d_in[4];
    const float* du1 = (const float*)d_in[5];
    const float* dv1 = (const float*)d_in[6];
    const float* du2 = (const float*)d_in[7];
    const float* dv2 = (const float*)d_in[8];
    const float* du3 = (const float*)d_in[9];
    const float* dv3 = (const float*)d_in[10];
    float* out = (float*)d_out;

    float *p_bg, *p_bu, *p_hm, *p_t1, *p_t3, *p_lg;
    cudaGetSymbolAddress((void**)&p_bg, g_base_gate);
    cudaGetSymbolAddress((void**)&p_bu, g_base_up);
    cudaGetSymbolAddress((void**)&p_hm, g_hmid);
    cudaGetSymbolAddress((void**)&p_t1, g_t1);
    cudaGetSymbolAddress((void**)&p_t3, g_t3);
    cudaGetSymbolAddress((void**)&p_lg, g_logits_s);

    // Output layout: final [T,H] first, then router_logits [T,E] if room.
    float* logits = (out_size >= TT * HH + TT * EE) ? (out + (size_t)TT * HH) : p_lg;

    init_counts<<<1, 32>>>();
    router_kernel<<<TT / 8, 256>>>(x, gw, logits);

    // base_gate = X @ Wm1^T ; base_up = X @ Wm3^T
    sgemm_nt<false><<<dim3(II / 128, TT / 128), 256>>>(x, Wm1, p_bg, TT, II, HH);
    sgemm_nt<false><<<dim3(II / 128, TT / 128), 256>>>(x, Wm3, p_bu, TT, II, HH);

    // t1 = X @ dv1^T (dense over all experts, N = E*R), t3 likewise
    sgemm_nt<false><<<dim3((ERR + 127) / 128, TT / 128), 256>>>(x, dv1, p_t1, TT, ERR, HH);
    sgemm_nt<false><<<dim3((ERR + 127) / 128, TT / 128), 256>>>(x, dv3, p_t3, TT, ERR, HH);

    // hmid[slot] = w * silu(base_gate + du1@t1) * (base_up + du3@t3)
    expert_gateup_kernel<<<dim3(II / 64, TT / 64, EE), 256>>>(du1, du3);

    // t2[slot] = hmid[slot] @ dv2[e]^T
    expert_t2_kernel<<<dim3((RR + 63) / 64, TT / 64, EE), 256>>>(dv2);

    // final = (hmid_slot0 + hmid_slot1) @ Wm2^T
    sgemm_nt<true><<<dim3(HH / 128, TT / 128), 256>>>(p_hm, Wm2, out, TT, HH, II);

    // final += t2[slot] @ du2[e]^T
    expert_down_kernel<<<dim3(HH / 64, TT / 64, EE), 256>>>(du2, out);
}

// round 3
// speedup vs baseline: 1.7248x; 1.7248x over previous
#include <cuda_runtime.h>
#include <math.h>
#include <stdint.h>

// Problem constants
#define TT 1024            // tokens (B*S)
#define HH 2048            // hidden
#define II 7168            // intermediate
#define EE 8               // experts
#define RR 159             // low rank
#define ERR (EE * RR)      // 1272

// ---------------------------------------------------------------------------
// Scratch (device globals; no runtime allocation allowed)
// ---------------------------------------------------------------------------
__device__ float g_base_gate[(size_t)TT * II];
__device__ float g_base_up  [(size_t)TT * II];
__device__ float g_hmid     [(size_t)TT * 2 * II];  // indexed by slot = t*2+k
__device__ float g_hsum     [(size_t)TT * II];      // hmid slot0+slot1
__device__ float g_t1       [(size_t)TT * ERR];
__device__ float g_t3       [(size_t)TT * ERR];
__device__ float g_t2       [(size_t)TT * 2 * RR];
__device__ float g_w        [TT * 2];
__device__ int   g_elist    [EE][TT];
__device__ int   g_ecount   [EE];
__device__ float g_logits_s [TT * EE];

// ---------------------------------------------------------------------------
// Helpers
// ---------------------------------------------------------------------------
__device__ __forceinline__ uint32_t smem_u32(const void* p) {
    uint32_t a;
    asm("{ .reg .u64 t; cvta.to.shared.u64 t, %1; cvt.u32.u64 %0, t; }"
        : "=r"(a) : "l"(p));
    return a;
}
__device__ __forceinline__ uint32_t f2tf32(float f) {
    uint32_t r;
    asm("cvt.rna.tf32.f32 %0, %1;" : "=r"(r) : "f"(f));
    return r;
}
__device__ __forceinline__ void cp_async16(uint32_t s, const void* g) {
    asm volatile("cp.async.cg.shared.global [%0], [%1], 16;" :: "r"(s), "l"(g));
}
#define CP_COMMIT() asm volatile("cp.async.commit_group;" ::: "memory")
#define CP_WAIT(n)  asm volatile("cp.async.wait_group %0;" :: "n"(n) : "memory")

__device__ __forceinline__ void mma_tf32(float* c, const uint32_t* a,
                                         uint32_t b0, uint32_t b1) {
    asm volatile(
        "mma.sync.aligned.m16n8k8.row.col.f32.tf32.tf32.f32 "
        "{%0,%1,%2,%3}, {%4,%5,%6,%7}, {%8,%9}, {%0,%1,%2,%3};"
        : "+f"(c[0]), "+f"(c[1]), "+f"(c[2]), "+f"(c[3])
        : "r"(a[0]), "r"(a[1]), "r"(a[2]), "r"(a[3]), "r"(b0), "r"(b1));
}

// ---------------------------------------------------------------------------
// tf32 mma.sync GEMM NT: C[M,N] = A[M,K] @ B[N,K]^T
// 128x128x32 tiles, 256 threads (8 warps: 4m x 2n), cp.async double buffer.
// blockIdx.z selects (B0,C0) or (B1,C1) so paired GEMMs fill the chip.
// Requires: M % 128 == 0, K % 32 == 0. N arbitrary (clamped loads, guarded
// stores; clamped B columns produce garbage accumulators that are never
// stored and stay finite).
// ---------------------------------------------------------------------------
#define BK 32
#define LDS_STRIDE 36                     // floats per smem row (32 + 4 pad)
#define TILE_FLOATS (128 * LDS_STRIDE)    // 4608
#define TCP_SMEM_BYTES (4 * TILE_FLOATS * 4)  // 73728

__device__ __forceinline__ void load_chunk(const float* __restrict__ A,
                                           const float* __restrict__ B,
                                           int N, int K, int bm, int bn, int k0,
                                           uint32_t sA, uint32_t sB, int tid) {
#pragma unroll
    for (int i = 0; i < 4; i++) {
        int idx = tid + i * 256;
        int row = idx >> 3;
        int seg = idx & 7;
        const float* src = A + (size_t)(bm + row) * K + k0 + seg * 4;
        cp_async16(sA + row * (LDS_STRIDE * 4) + seg * 16, src);
    }
#pragma unroll
    for (int i = 0; i < 4; i++) {
        int idx = tid + i * 256;
        int row = idx >> 3;
        int seg = idx & 7;
        int gn = bn + row;
        if (gn > N - 1) gn = N - 1;           // clamp: valid finite data
        const float* src = B + (size_t)gn * K + k0 + seg * 4;
        cp_async16(sB + row * (LDS_STRIDE * 4) + seg * 16, src);
    }
}

__global__ void __launch_bounds__(256, 2)
tc_pair(const float* __restrict__ A,
        const float* __restrict__ B0, const float* __restrict__ B1,
        float* __restrict__ C0, float* __restrict__ C1,
        int N, int K) {
    const float* B = (blockIdx.z == 0) ? B0 : B1;
    float* C = (blockIdx.z == 0) ? C0 : C1;

    extern __shared__ float smem[];
    float* As[2] = {smem, smem + TILE_FLOATS};
    float* Bs[2] = {smem + 2 * TILE_FLOATS, smem + 3 * TILE_FLOATS};
    const uint32_t sA[2] = {smem_u32(As[0]), smem_u32(As[1])};
    const uint32_t sB[2] = {smem_u32(Bs[0]), smem_u32(Bs[1])};

    const int tid = threadIdx.x;
    const int wid = tid >> 5;
    const int lane = tid & 31;
    const int g = lane >> 2;      // group id (row within 8)
    const int t = lane & 3;       // thread in group (k quarter)
    const int mbase = (wid & 3) * 32;
    const int nbase = (wid >> 2) * 64;
    const int bm = blockIdx.y * 128;
    const int bn = blockIdx.x * 128;

    float acc[2][8][4];
#pragma unroll
    for (int i = 0; i < 2; i++)
#pragma unroll
        for (int j = 0; j < 8; j++)
#pragma unroll
            for (int v = 0; v < 4; v++) acc[i][j][v] = 0.f;

    const int CH = K / BK;

    load_chunk(A, B, N, K, bm, bn, 0, sA[0], sB[0], tid);
    CP_COMMIT();

    for (int c = 0; c < CH; c++) {
        int p = c & 1;
        if (c + 1 < CH) {
            load_chunk(A, B, N, K, bm, bn, (c + 1) * BK,
                       sA[p ^ 1], sB[p ^ 1], tid);
            CP_COMMIT();
            CP_WAIT(1);
        } else {
            CP_WAIT(0);
        }
        __syncthreads();

        const float* a_s = As[p];
        const float* b_s = Bs[p];
#pragma unroll
        for (int ks = 0; ks < 4; ks++) {
            const int k = ks * 8;
            uint32_t af[2][4];
#pragma unroll
            for (int i = 0; i < 2; i++) {
                int r = mbase + i * 16 + g;
                af[i][0] = f2tf32(a_s[r * LDS_STRIDE + k + t]);
                af[i][1] = f2tf32(a_s[(r + 8) * LDS_STRIDE + k + t]);
                af[i][2] = f2tf32(a_s[r * LDS_STRIDE + k + t + 4]);
                af[i][3] = f2tf32(a_s[(r + 8) * LDS_STRIDE + k + t + 4]);
            }
#pragma unroll
            for (int j = 0; j < 8; j++) {
                int rb = nbase + j * 8 + g;
                uint32_t b0 = f2tf32(b_s[rb * LDS_STRIDE + k + t]);
                uint32_t b1 = f2tf32(b_s[rb * LDS_STRIDE + k + t + 4]);
#pragma unroll
                for (int i = 0; i < 2; i++) mma_tf32(acc[i][j], af[i], b0, b1);
            }
        }
        __syncthreads();
    }

    // Epilogue: c0,c1 at (row, col..col+1); c2,c3 at (row+8, col..col+1)
#pragma unroll
    for (int i = 0; i < 2; i++) {
        int row = bm + mbase + i * 16 + g;
#pragma unroll
        for (int j = 0; j < 8; j++) {
            int col = bn + nbase + j * 8 + 2 * t;
            if (col < N) {   // N is even; col is even -> pair in bounds
                float2 v0 = make_float2(acc[i][j][0], acc[i][j][1]);
                float2 v1 = make_float2(acc[i][j][2], acc[i][j][3]);
                *(float2*)(C + (size_t)row * N + col) = v0;
                *(float2*)(C + (size_t)(row + 8) * N + col) = v1;
            }
        }
    }
}

// ---------------------------------------------------------------------------
// hsum: g_hsum[t, i] = g_hmid[t*2, i] + g_hmid[t*2+1, i]
// ---------------------------------------------------------------------------
__global__ void hsum_kernel() {
    size_t idx = ((size_t)blockIdx.x * blockDim.x + threadIdx.x) * 4;
    int t = (int)(idx / II);
    int i = (int)(idx % II);
    const float4 a = *(const float4*)&g_hmid[(size_t)(t * 2) * II + i];
    const float4 b = *(const float4*)&g_hmid[(size_t)(t * 2 + 1) * II + i];
    float4 s = make_float4(a.x + b.x, a.y + b.y, a.z + b.z, a.w + b.w);
    *(float4*)&g_hsum[idx] = s;
}

// ---------------------------------------------------------------------------
// Init: zero expert counters (must happen each replay)
// ---------------------------------------------------------------------------
__global__ void init_counts() {
    if (threadIdx.x < EE) g_ecount[threadIdx.x] = 0;
}

// ---------------------------------------------------------------------------
// Router: one warp per token.
// ---------------------------------------------------------------------------
__global__ void router_kernel(const float* __restrict__ x,
                              const float* __restrict__ gw,
                              float* __restrict__ logits_out) {
    int warp = threadIdx.x >> 5;
    int lane = threadIdx.x & 31;
    int t = blockIdx.x * (blockDim.x >> 5) + warp;
    if (t >= TT) return;
    const float* xr = x + (size_t)t * HH;
    float lg[EE];
#pragma unroll
    for (int e = 0; e < EE; e++) {
        const float* w = gw + e * HH;
        float s = 0.f;
        for (int h = lane; h < HH; h += 32) s += xr[h] * w[h];
#pragma unroll
        for (int o = 16; o > 0; o >>= 1) s += __shfl_xor_sync(0xffffffffu, s, o);
        lg[e] = s;
    }
    if (lane == 0) {
#pragma unroll
        for (int e = 0; e < EE; e++) logits_out[t * EE + e] = lg[e];
        int i0 = 0;
#pragma unroll
        for (int e = 1; e < EE; e++) if (lg[e] > lg[i0]) i0 = e;
        int i1 = (i0 == 0) ? 1 : 0;
#pragma unroll
        for (int e = 0; e < EE; e++) if (e != i0 && lg[e] > lg[i1]) i1 = e;
        float r = expf(lg[i1] - lg[i0]);
        float w0 = 1.f / (1.f + r);
        float w1 = r / (1.f + r);
        g_w[t * 2 + 0] = w0;
        g_w[t * 2 + 1] = w1;
        int p0 = atomicAdd(&g_ecount[i0], 1);
        g_elist[i0][p0] = t * 2 + 0;
        int p1 = atomicAdd(&g_ecount[i1], 1);
        g_elist[i1][p1] = t * 2 + 1;
    }
}

// ---------------------------------------------------------------------------
// Per-expert gathered GEMM (dual): dG = t1_e @ du1[e]^T, dU = t3_e @ du3[e]^T
// Epilogue: hmid[slot, i] = w * silu(base_gate + dG) * (base_up + dU)
// ---------------------------------------------------------------------------
__global__ void __launch_bounds__(256) expert_gateup_kernel(const float* __restrict__ du1,
                                                            const float* __restrict__ du3) {
    const int e = blockIdx.z;
    const int ne = g_ecount[e];
    const int m0 = blockIdx.y * 64;
    if (m0 >= ne) return;
    const int n0 = blockIdx.x * 64;

    __shared__ int   s_tk[64];
    __shared__ float s_w[64];
    __shared__ float A1s[16][68], A3s[16][68], B1s[16][68], B3s[16][68];

    const int tid = threadIdx.x;
    if (tid < 64) {
        int gm = m0 + tid;
        if (gm < ne) {
            int tk = g_elist[e][gm];
            s_tk[tid] = tk;
            s_w[tid] = g_w[tk];
        } else {
            s_tk[tid] = -1;
            s_w[tid] = 0.f;
        }
    }
    __syncthreads();

    const int tx = tid & 15;
    const int ty = tid >> 4;
    const float* du1e = du1 + (size_t)e * II * RR;
    const float* du3e = du3 + (size_t)e * II * RR;

    float acc1[4][4] = {}, acc3[4][4] = {};

    for (int k0 = 0; k0 < RR; k0 += 16) {
#pragma unroll
        for (int i = 0; i < 4; i++) {
            int elem = tid + i * 256;
            int r = elem >> 4;
            int kk = elem & 15;
            int k = k0 + kk;
            int tk = s_tk[r];
            float v1 = 0.f, v3 = 0.f;
            if (tk >= 0 && k < RR) {
                size_t off = (size_t)(tk >> 1) * ERR + (size_t)e * RR + k;
                v1 = g_t1[off];
                v3 = g_t3[off];
            }
            A1s[kk][r] = v1; A3s[kk][r] = v3;
            float b1 = 0.f, b3 = 0.f;
            if (k < RR) {
                size_t boff = (size_t)(n0 + r) * RR + k;
                b1 = du1e[boff]; b3 = du3e[boff];
            }
            B1s[kk][r] = b1; B3s[kk][r] = b3;
        }
        __syncthreads();
#pragma unroll
        for (int kk = 0; kk < 16; kk++) {
            float4 a1 = *(const float4*)&A1s[kk][ty * 4];
            float4 a3 = *(const float4*)&A3s[kk][ty * 4];
            float4 b1 = *(const float4*)&B1s[kk][tx * 4];
            float4 b3 = *(const float4*)&B3s[kk][tx * 4];
            float a1v[4] = {a1.x, a1.y, a1.z, a1.w};
            float a3v[4] = {a3.x, a3.y, a3.z, a3.w};
            float b1v[4] = {b1.x, b1.y, b1.z, b1.w};
            float b3v[4] = {b3.x, b3.y, b3.z, b3.w};
#pragma unroll
            for (int i = 0; i < 4; i++)
#pragma unroll
                for (int j = 0; j < 4; j++) {
                    acc1[i][j] += a1v[i] * b1v[j];
                    acc3[i][j] += a3v[i] * b3v[j];
                }
        }
        __syncthreads();
    }

#pragma unroll
    for (int i = 0; i < 4; i++) {
        int r = ty * 4 + i;
        int tk = s_tk[r];
        if (tk < 0) continue;
        int t = tk >> 1;
        float w = s_w[r];
#pragma unroll
        for (int j = 0; j < 4; j++) {
            int gi = n0 + tx * 4 + j;
            size_t off = (size_t)t * II + gi;
            float g = g_base_gate[off] + acc1[i][j];
            float u = g_base_up[off]  + acc3[i][j];
            float s = g / (1.f + expf(-g));
            g_hmid[(size_t)tk * II + gi] = w * s * u;
        }
    }
}

// ---------------------------------------------------------------------------
// Per-expert gathered GEMM: t2[slot, r] = hmid[slot, :] . dv2[e, r, :]  (K = I)
// ---------------------------------------------------------------------------
__global__ void __launch_bounds__(256) expert_t2_kernel(const float* __restrict__ dv2) {
    const int e = blockIdx.z;
    const int ne = g_ecount[e];
    const int m0 = blockIdx.y * 64;
    if (m0 >= ne) return;
    const int n0 = blockIdx.x * 64;

    __shared__ int   s_tk[64];
    __shared__ float As[16][68], Bs[16][68];

    const int tid = threadIdx.x;
    if (tid < 64) {
        int gm = m0 + tid;
        s_tk[tid] = (gm < ne) ? g_elist[e][gm] : -1;
    }
    __syncthreads();

    const int tx = tid & 15;
    const int ty = tid >> 4;
    const float* dv2e = dv2 + (size_t)e * RR * II;

    float acc[4][4] = {};

    for (int k0 = 0; k0 < II; k0 += 16) {
#pragma unroll
        for (int i = 0; i < 4; i++) {
            int elem = tid + i * 256;
            int r = elem >> 4;
            int kk = elem & 15;
            int k = k0 + kk;
            int tk = s_tk[r];
            As[kk][r] = (tk >= 0) ? g_hmid[(size_t)tk * II + k] : 0.f;
            int gr = n0 + r;
            Bs[kk][r] = (gr < RR) ? dv2e[(size_t)gr * II + k] : 0.f;
        }
        __syncthreads();
#pragma unroll
        for (int kk = 0; kk < 16; kk++) {
            float4 a = *(const float4*)&As[kk][ty * 4];
            float4 b = *(const float4*)&Bs[kk][tx * 4];
            float av[4] = {a.x, a.y, a.z, a.w};
            float bv[4] = {b.x, b.y, b.z, b.w};
#pragma unroll
            for (int i = 0; i < 4; i++)
#pragma unroll
                for (int j = 0; j < 4; j++) acc[i][j] += av[i] * bv[j];
        }
        __syncthreads();
    }

#pragma unroll
    for (int i = 0; i < 4; i++) {
        int tk = s_tk[ty * 4 + i];
        if (tk < 0) continue;
#pragma unroll
        for (int j = 0; j < 4; j++) {
            int gr = n0 + tx * 4 + j;
            if (gr < RR) g_t2[(size_t)tk * RR + gr] = acc[i][j];
        }
    }
}

// ---------------------------------------------------------------------------
// Per-expert gathered GEMM: out[t, h] += t2[slot, :] . du2[e, h, :]  (K = R)
// ---------------------------------------------------------------------------
__global__ void __launch_bounds__(256) expert_down_kernel(const float* __restrict__ du2,
                                                          float* __restrict__ out) {
    const int e = blockIdx.z;
    const int ne = g_ecount[e];
    const int m0 = blockIdx.y * 64;
    if (m0 >= ne) return;
    const int n0 = blockIdx.x * 64;

    __shared__ int   s_tk[64];
    __shared__ float As[16][68], Bs[16][68];

    const int tid = threadIdx.x;
    if (tid < 64) {
        int gm = m0 + tid;
        s_tk[tid] = (gm < ne) ? g_elist[e][gm] : -1;
    }
    __syncthreads();

    const int tx = tid & 15;
    const int ty = tid >> 4;
    const float* du2e = du2 + (size_t)e * HH * RR;

    float acc[4][4] = {};

    for (int k0 = 0; k0 < RR; k0 += 16) {
#pragma unroll
        for (int i = 0; i < 4; i++) {
            int elem = tid + i * 256;
            int r = elem >> 4;
            int kk = elem & 15;
            int k = k0 + kk;
            int tk = s_tk[r];
            As[kk][r] = (tk >= 0 && k < RR) ? g_t2[(size_t)tk * RR + k] : 0.f;
            Bs[kk][r] = (k < RR) ? du2e[(size_t)(n0 + r) * RR + k] : 0.f;
        }
        __syncthreads();
#pragma unroll
        for (int kk = 0; kk < 16; kk++) {
            float4 a = *(const float4*)&As[kk][ty * 4];
            float4 b = *(const float4*)&Bs[kk][tx * 4];
            float av[4] = {a.x, a.y, a.z, a.w};
            float bv[4] = {b.x, b.y, b.z, b.w};
#pragma unroll
            for (int i = 0; i < 4; i++)
#pragma unroll
                for (int j = 0; j < 4; j++) acc[i][j] += av[i] * bv[j];
        }
        __syncthreads();
    }

#pragma unroll
    for (int i = 0; i < 4; i++) {
        int tk = s_tk[ty * 4 + i];
        if (tk < 0) continue;
        int t = tk >> 1;
#pragma unroll
        for (int j = 0; j < 4; j++) {
            int gh = n0 + tx * 4 + j;
            atomicAdd(&out[(size_t)t * HH + gh], acc[i][j]);
        }
    }
}

// ---------------------------------------------------------------------------
// Launch
// ---------------------------------------------------------------------------
extern "C" void kernel_launch(void* const* d_in, const int* in_sizes, int n_in,
                              void* d_out, int out_size) {
    (void)in_sizes; (void)n_in;
    const float* x   = (const float*)d_in[0];
    const float* gw  = (const float*)d_in[1];
    const float* Wm1 = (const float*)d_in[2];
    const float* Wm2 = (const float*)d_in[3];
    const float* Wm3 = (const float*)d_in[4];
    const float* du1 = (const float*)d_in[5];
    const float* dv1 = (const float*)d_in[6];
    const float* du2 = (const float*)d_in[7];
    const float* dv2 = (const float*)d_in[8];
    const float* du3 = (const float*)d_in[9];
    const float* dv3 = (const float*)d_in[10];
    float* out = (float*)d_out;

    float *p_bg, *p_bu, *p_hs, *p_t1, *p_t3, *p_lg;
    cudaGetSymbolAddress((void**)&p_bg, g_base_gate);
    cudaGetSymbolAddress((void**)&p_bu, g_base_up);
    cudaGetSymbolAddress((void**)&p_hs, g_hsum);
    cudaGetSymbolAddress((void**)&p_t1, g_t1);
    cudaGetSymbolAddress((void**)&p_t3, g_t3);
    cudaGetSymbolAddress((void**)&p_lg, g_logits_s);

    cudaFuncSetAttribute(tc_pair, cudaFuncAttributeMaxDynamicSharedMemorySize,
                         TCP_SMEM_BYTES);

    float* logits = (out_size >= TT * HH + TT * EE) ? (out + (size_t)TT * HH) : p_lg;

    init_counts<<<1, 32>>>();
    router_kernel<<<TT / 8, 256>>>(x, gw, logits);

    // base_gate = X @ Wm1^T ; base_up = X @ Wm3^T   (one launch, z picks)
    tc_pair<<<dim3(II / 128, TT / 128, 2), 256, TCP_SMEM_BYTES>>>(
        x, Wm1, Wm3, p_bg, p_bu, II, HH);

    // t1 = X @ dv1^T ; t3 = X @ dv3^T   (N = E*R = 1272)
    tc_pair<<<dim3((ERR + 127) / 128, TT / 128, 2), 256, TCP_SMEM_BYTES>>>(
        x, dv1, dv3, p_t1, p_t3, ERR, HH);

    // hmid[slot] = w * silu(base_gate + du1@t1) * (base_up + du3@t3)
    expert_gateup_kernel<<<dim3(II / 64, TT / 64, EE), 256>>>(du1, du3);

    // t2[slot] = hmid[slot] @ dv2[e]^T
    expert_t2_kernel<<<dim3((RR + 63) / 64, TT / 64, EE), 256>>>(dv2);

    // hsum = hmid slot0 + slot1
    hsum_kernel<<<(TT * II) / (256 * 4), 256>>>();

    // final = hsum @ Wm2^T
    tc_pair<<<dim3(HH / 128, TT / 128, 1), 256, TCP_SMEM_BYTES>>>(
        p_hs, Wm2, Wm2, out, out, HH, II);

    // final += t2[slot] @ du2[e]^T
    expert_down_kernel<<<dim3(HH / 64, TT / 64, EE), 256>>>(du2, out);
}